// round 14
// baseline (speedup 1.0000x reference)
#include <cuda_runtime.h>
#include <cstddef>

#define SDIM 256
#define LDIM 65536
#define CDIM 64
#define CODIM 64

typedef unsigned long long ull;

__device__ __forceinline__ ull pack2(float v) {
    ull r; asm("mov.b64 %0, {%1, %1};" : "=l"(r) : "f"(v)); return r;
}
__device__ __forceinline__ ull pack2(float a, float b) {
    ull r; asm("mov.b64 %0, {%1, %2};" : "=l"(r) : "f"(a), "f"(b)); return r;
}
__device__ __forceinline__ ull fma2(ull a, ull b, ull c) {
    ull d; asm("fma.rn.f32x2 %0, %1, %2, %3;" : "=l"(d) : "l"(a), "l"(b), "l"(c)); return d;
}
__device__ __forceinline__ void unpack2(ull v, float &lo, float &hi) {
    asm("mov.b64 {%0, %1}, %2;" : "=f"(lo), "=f"(hi) : "l"(v));
}

// Algebraic collapse of reference:
//   fold(weight * unfold(x))[c,l] = x[c,l] * sum_{t in 3x3} weight[c*9+t, l+off_t]
//   (the x index is tap-independent, so unfold/fold never materialize)
//   y[o,l] = sum_c conv[c*64+o] * h2[c,l]
// One block per image row p. Phase 1 streams weight (each element read exactly
// once, __ldcs) into h2[64][256] in smem; Phase 2 is a register-tiled
// 64x64 * 64x256 channel-mix GEMM using packed fma.rn.f32x2.
extern "C" __global__ void __launch_bounds__(256, 2)
reverb_fused(const float* __restrict__ x,
             const float* __restrict__ w,
             const float* __restrict__ conv,
             float* __restrict__ out)
{
    extern __shared__ float smem[];
    float* convs = smem;                  // 64*64 floats = 16 KB
    float* h2s   = smem + CDIM * CODIM;   // 64*256 floats = 64 KB

    const int tid = threadIdx.x;
    const int p   = blockIdx.x;
    const int q   = tid;
    const int l   = p * SDIM + q;

    // Stage conv (reused 64x per block) into smem
    {
        float4* dst       = (float4*)convs;
        const float4* src = (const float4*)conv;
        #pragma unroll
        for (int i = 0; i < 4; ++i)
            dst[tid + 256 * i] = src[tid + 256 * i];
    }

    const bool left  = (q > 0);
    const bool right = (q < SDIM - 1);
    const bool up    = (p > 0);          // uniform per block
    const bool down  = (p < SDIM - 1);   // uniform per block

    // Phase 1: 9 shifted, masked weight taps per channel.
    // tap t = ki*3+kj reads weight[(c*9+t), l + (1-ki)*256 + (1-kj)]
    #pragma unroll 2
    for (int c = 0; c < CDIM; ++c) {
        const float* wp = w + (size_t)c * 9u * LDIM + l;
        float xs = __ldcs(&x[c * LDIM + l]);
        float s  = __ldcs(wp + 4 * LDIM);                              // (1,1)
        float a  = left  ? __ldcs(wp + 5 * LDIM - 1) : 0.f;            // (1,2)
        float b  = right ? __ldcs(wp + 3 * LDIM + 1) : 0.f;            // (1,0)
        float u0 = 0.f, u1 = 0.f, u2 = 0.f;
        float d0 = 0.f, d1 = 0.f, d2 = 0.f;
        if (up) {
            u0 = __ldcs(wp + 7 * LDIM - SDIM);                         // (2,1)
            u1 = left  ? __ldcs(wp + 8 * LDIM - SDIM - 1) : 0.f;       // (2,2)
            u2 = right ? __ldcs(wp + 6 * LDIM - SDIM + 1) : 0.f;       // (2,0)
        }
        if (down) {
            d0 = __ldcs(wp + 1 * LDIM + SDIM);                         // (0,1)
            d1 = left  ? __ldcs(wp + 2 * LDIM + SDIM - 1) : 0.f;       // (0,2)
            d2 = right ? __ldcs(wp + 0 * LDIM + SDIM + 1) : 0.f;       // (0,0)
        }
        float sum = ((s + a) + (b + u0)) + ((u1 + u2) + (d0 + (d1 + d2)));
        h2s[c * SDIM + q] = xs * sum;
    }
    __syncthreads();

    // Phase 2: each thread owns 8 output channels (ot*8..+7) x 8 pixels (lt+32k).
    // Packed f32x2 FMAs: lane pair = (o, o+1); h2 value broadcast into both lanes.
    const int lt = tid & 31;
    const int ot = tid >> 5;

    ull acc[4][8];
    #pragma unroll
    for (int j = 0; j < 4; ++j)
        #pragma unroll
        for (int k = 0; k < 8; ++k)
            acc[j][k] = 0ull;

    #pragma unroll 2
    for (int c = 0; c < CDIM; ++c) {
        const float* crow = convs + c * CODIM + ot * 8;
        float4 a0 = *(const float4*)(crow);        // warp-broadcast LDS.128
        float4 a1 = *(const float4*)(crow + 4);
        ull ap[4];
        ap[0] = pack2(a0.x, a0.y);
        ap[1] = pack2(a0.z, a0.w);
        ap[2] = pack2(a1.x, a1.y);
        ap[3] = pack2(a1.z, a1.w);

        const float* brow = h2s + c * SDIM + lt;   // stride-1 lanes, conflict-free
        ull vv[8];
        #pragma unroll
        for (int k = 0; k < 8; ++k) vv[k] = pack2(brow[32 * k]);

        #pragma unroll
        for (int k = 0; k < 8; ++k) {
            acc[0][k] = fma2(ap[0], vv[k], acc[0][k]);
            acc[1][k] = fma2(ap[1], vv[k], acc[1][k]);
            acc[2][k] = fma2(ap[2], vv[k], acc[2][k]);
            acc[3][k] = fma2(ap[3], vv[k], acc[3][k]);
        }
    }

    // Epilogue: coalesced streaming stores.
    #pragma unroll
    for (int j = 0; j < 4; ++j) {
        const int olo = ot * 8 + 2 * j;
        float* plo = out + (size_t)olo * LDIM + p * SDIM + lt;
        float* phi = plo + LDIM;
        #pragma unroll
        for (int k = 0; k < 8; ++k) {
            float lo, hi; unpack2(acc[j][k], lo, hi);
            __stcs(plo + 32 * k, lo);
            __stcs(phi + 32 * k, hi);
        }
    }
}

extern "C" void kernel_launch(void* const* d_in, const int* in_sizes, int n_in,
                              void* d_out, int out_size) {
    // Route inputs by element count (robust to ordering), with positional fallback:
    // x: 64*65536 = 4194304, weight: 576*65536 = 37748736, conv: 64*64 = 4096
    const float* x  = nullptr;
    const float* w  = nullptr;
    const float* cv = nullptr;
    for (int i = 0; i < n_in; ++i) {
        if      (in_sizes[i] == CDIM * LDIM)      x  = (const float*)d_in[i];
        else if (in_sizes[i] == CDIM * 9 * LDIM)  w  = (const float*)d_in[i];
        else if (in_sizes[i] == CDIM * CODIM)     cv = (const float*)d_in[i];
    }
    if (!x || !w || !cv) {                         // metadata order: x, weight, conv
        x  = (const float*)d_in[0];
        w  = (const float*)d_in[1];
        cv = (const float*)d_in[2];
    }
    const int smem_bytes = (CDIM * CODIM + CDIM * SDIM) * (int)sizeof(float); // 81920
    // Unconditional (no static guard — harness forbids call-count-dependent
    // behavior). Host-side attribute set; not a stream op, so capture-safe.
    cudaFuncSetAttribute(reverb_fused, cudaFuncAttributeMaxDynamicSharedMemorySize, smem_bytes);
    reverb_fused<<<SDIM, 256, smem_bytes>>>(x, w, cv, (float*)d_out);
}

// round 15
// speedup vs baseline: 1.3650x; 1.3650x over previous
#include <cuda_runtime.h>
#include <cstddef>

#define SDIM 256
#define HDIM 128          // pixels per block (half row)
#define LDIM 65536
#define CDIM 64
#define CODIM 64

typedef unsigned long long ull;

__device__ __forceinline__ ull pack2(float v) {
    ull r; asm("mov.b64 %0, {%1, %1};" : "=l"(r) : "f"(v)); return r;
}
__device__ __forceinline__ ull pack2(float a, float b) {
    ull r; asm("mov.b64 %0, {%1, %2};" : "=l"(r) : "f"(a), "f"(b)); return r;
}
__device__ __forceinline__ ull fma2(ull a, ull b, ull c) {
    ull d; asm("fma.rn.f32x2 %0, %1, %2, %3;" : "=l"(d) : "l"(a), "l"(b), "l"(c)); return d;
}
__device__ __forceinline__ void unpack2(ull v, float &lo, float &hi) {
    asm("mov.b64 {%0, %1}, %2;" : "=f"(lo), "=f"(hi) : "l"(v));
}

// h2[c,l] = x[c,l] * sum_{t in 3x3} weight[c*9+t, l+off_t]  (boundary-masked)
// y[o,l]  = sum_c conv[c*64+o] * h2[c,l]
// 512 blocks: block handles half a row (128 pixels) to fit 4 CTAs/SM
// (48 KB smem, <=64 regs) -> 32 warps/SM for 2x the memory concurrency of R14.
extern "C" __global__ void __launch_bounds__(256, 4)
reverb_fused(const float* __restrict__ x,
             const float* __restrict__ w,
             const float* __restrict__ conv,
             float* __restrict__ out)
{
    extern __shared__ float smem[];
    float* convs = smem;                  // 64*64 floats = 16 KB
    float* h2s   = smem + CDIM * CODIM;   // 64*128 floats = 32 KB

    const int tid = threadIdx.x;
    const int p   = blockIdx.x >> 1;
    const int q0  = (blockIdx.x & 1) << 7;

    // Stage conv (reused 32x per block) into smem
    {
        float4* dst       = (float4*)convs;
        const float4* src = (const float4*)conv;
        #pragma unroll
        for (int i = 0; i < 4; ++i)
            dst[tid + 256 * i] = src[tid + 256 * i];
    }

    // Phase 1: 256 threads = 2 channel-halves x 128 pixels.
    const int half = tid >> 7;            // 0 or 1 -> channels [half*32, half*32+32)
    const int qi   = tid & 127;
    const int q    = q0 + qi;
    const int l    = p * SDIM + q;

    const bool left  = (q > 0);
    const bool right = (q < SDIM - 1);
    const bool up    = (p > 0);           // uniform per block
    const bool down  = (p < SDIM - 1);    // uniform per block

    // tap t = ki*3+kj reads weight[(c*9+t), l + (1-ki)*256 + (1-kj)]
    #pragma unroll 2
    for (int ci = 0; ci < 32; ++ci) {
        const int c = half * 32 + ci;
        const float* wp = w + (size_t)c * 9u * LDIM + l;
        float xs = __ldcs(&x[c * LDIM + l]);
        float s  = __ldcs(wp + 4 * LDIM);                              // (1,1)
        float a  = left  ? __ldcs(wp + 5 * LDIM - 1) : 0.f;            // (1,2)
        float b  = right ? __ldcs(wp + 3 * LDIM + 1) : 0.f;            // (1,0)
        float u0 = 0.f, u1 = 0.f, u2 = 0.f;
        float d0 = 0.f, d1 = 0.f, d2 = 0.f;
        if (up) {
            u0 = __ldcs(wp + 7 * LDIM - SDIM);                         // (2,1)
            u1 = left  ? __ldcs(wp + 8 * LDIM - SDIM - 1) : 0.f;       // (2,2)
            u2 = right ? __ldcs(wp + 6 * LDIM - SDIM + 1) : 0.f;       // (2,0)
        }
        if (down) {
            d0 = __ldcs(wp + 1 * LDIM + SDIM);                         // (0,1)
            d1 = left  ? __ldcs(wp + 2 * LDIM + SDIM - 1) : 0.f;       // (0,2)
            d2 = right ? __ldcs(wp + 0 * LDIM + SDIM + 1) : 0.f;       // (0,0)
        }
        float sum = ((s + a) + (b + u0)) + ((u1 + u2) + (d0 + (d1 + d2)));
        h2s[c * HDIM + qi] = xs * sum;
    }
    __syncthreads();

    // Phase 2: warp ot owns 8 out-channels; lane lt owns pixels lt+32k (k<4).
    const int lt = tid & 31;
    const int ot = tid >> 5;

    ull acc[4][4];
    #pragma unroll
    for (int j = 0; j < 4; ++j)
        #pragma unroll
        for (int k = 0; k < 4; ++k)
            acc[j][k] = 0ull;

    #pragma unroll 2
    for (int c = 0; c < CDIM; ++c) {
        const float* crow = convs + c * CODIM + ot * 8;
        float4 a0 = *(const float4*)(crow);        // warp-broadcast LDS.128
        float4 a1 = *(const float4*)(crow + 4);
        ull ap[4];
        ap[0] = pack2(a0.x, a0.y);
        ap[1] = pack2(a0.z, a0.w);
        ap[2] = pack2(a1.x, a1.y);
        ap[3] = pack2(a1.z, a1.w);

        const float* brow = h2s + c * HDIM + lt;   // stride-1 lanes, conflict-free
        ull vv[4];
        #pragma unroll
        for (int k = 0; k < 4; ++k) vv[k] = pack2(brow[32 * k]);

        #pragma unroll
        for (int k = 0; k < 4; ++k) {
            acc[0][k] = fma2(ap[0], vv[k], acc[0][k]);
            acc[1][k] = fma2(ap[1], vv[k], acc[1][k]);
            acc[2][k] = fma2(ap[2], vv[k], acc[2][k]);
            acc[3][k] = fma2(ap[3], vv[k], acc[3][k]);
        }
    }

    // Epilogue: coalesced streaming stores.
    #pragma unroll
    for (int j = 0; j < 4; ++j) {
        const int olo = ot * 8 + 2 * j;
        float* plo = out + (size_t)olo * LDIM + p * SDIM + q0 + lt;
        float* phi = plo + LDIM;
        #pragma unroll
        for (int k = 0; k < 4; ++k) {
            float lo, hi; unpack2(acc[j][k], lo, hi);
            __stcs(plo + 32 * k, lo);
            __stcs(phi + 32 * k, hi);
        }
    }
}

extern "C" void kernel_launch(void* const* d_in, const int* in_sizes, int n_in,
                              void* d_out, int out_size) {
    // Route inputs by element count (robust to ordering), with positional fallback:
    // x: 64*65536 = 4194304, weight: 576*65536 = 37748736, conv: 64*64 = 4096
    const float* x  = nullptr;
    const float* w  = nullptr;
    const float* cv = nullptr;
    for (int i = 0; i < n_in; ++i) {
        if      (in_sizes[i] == CDIM * LDIM)      x  = (const float*)d_in[i];
        else if (in_sizes[i] == CDIM * 9 * LDIM)  w  = (const float*)d_in[i];
        else if (in_sizes[i] == CDIM * CODIM)     cv = (const float*)d_in[i];
    }
    if (!x || !w || !cv) {                         // metadata order: x, weight, conv
        x  = (const float*)d_in[0];
        w  = (const float*)d_in[1];
        cv = (const float*)d_in[2];
    }
    const int smem_bytes = (CDIM * CODIM + CDIM * HDIM) * (int)sizeof(float); // 49152
    cudaFuncSetAttribute(reverb_fused, cudaFuncAttributeMaxDynamicSharedMemorySize, smem_bytes);
    reverb_fused<<<2 * SDIM, 256, smem_bytes>>>(x, w, cv, (float*)d_out);
}